// round 3
// baseline (speedup 1.0000x reference)
#include <cuda_runtime.h>
#include <cstdint>

#define CRF_B 512
#define CRF_S 1024
#define CRF_T 64
#define ROWS_PER_CTA 4        // 4 warps per CTA -> one warp per SMSP
#define NUM_CTAS (CRF_B / ROWS_PER_CTA)

__device__ float g_partial[CRF_B];

typedef unsigned long long u64;

__device__ __forceinline__ float ex2f(float x) {
    float r; asm("ex2.approx.f32 %0, %1;" : "=f"(r) : "f"(x)); return r;
}
__device__ __forceinline__ float lg2f(float x) {
    float r; asm("lg2.approx.f32 %0, %1;" : "=f"(r) : "f"(x)); return r;
}
__device__ __forceinline__ u64 pack2(float lo, float hi) {
    u64 r;
    asm("mov.b64 %0, {%1, %2};" : "=l"(r) : "f"(lo), "f"(hi));
    return r;
}
__device__ __forceinline__ void unpack2(u64 v, float& lo, float& hi) {
    asm("mov.b64 {%0, %1}, %2;" : "=f"(lo), "=f"(hi) : "l"(v));
}
// Packed dual-FMA: d.lo = a.lo*b.lo + c.lo ; d.hi = a.hi*b.hi + c.hi
__device__ __forceinline__ u64 ffma2(u64 a, u64 b, u64 c) {
    u64 d;
    asm("fma.rn.f32x2 %0, %1, %2, %3;" : "=l"(d) : "l"(a), "l"(b), "l"(c));
    return d;
}

__global__ __launch_bounds__(32 * ROWS_PER_CTA, 1)
void crf_main(const float* __restrict__ emis,
              const int*   __restrict__ tags,
              const float* __restrict__ mask,
              const float* __restrict__ trans)
{
    const int wid = threadIdx.x >> 5;        // row-within-CTA (one warp per row)
    const int j   = threadIdx.x & 31;        // lane: owns states 2j, 2j+1
    const int b   = blockIdx.x * ROWS_PER_CTA + wid;
    const int c0  = 2 * j;
    const int c1  = 2 * j + 1;

    // Per-row smem; no cross-warp sharing anywhere -> __syncwarp only.
    __shared__ __align__(16) float sE[ROWS_PER_CTA][2][CRF_T];  // double buffer
    __shared__ float sMref[ROWS_PER_CTA][2];

    const float LOG2E = 1.4426950408889634f;
    const float LN2   = 0.6931471805599453f;

    const float* mb    = mask + (size_t)b * CRF_S;
    const int*   tb    = tags + (size_t)b * CRF_S;
    const float* ebase = emis + (size_t)b * CRF_S * CRF_T;

    // ---------------- Gold score (gather, 32 lanes, all-lane result) --------
    float g = 0.f;
    for (int s = j; s < CRF_S; s += 32) {
        int   tg = tb[s];
        float ev = ebase[(size_t)s * CRF_T + tg];
        float term = (s == 0) ? ev : trans[tg * CRF_T + tb[s - 1]] + ev;
        g += term * mb[s];
    }
    #pragma unroll
    for (int off = 16; off; off >>= 1)
        g += __shfl_xor_sync(0xffffffffu, g, off);

    // ---------------- Texp columns c0, c1 -> 64 packed f32x2 registers ------
    u64 tA[CRF_T / 2], tB[CRF_T / 2];
    #pragma unroll
    for (int k = 0; k < CRF_T / 2; k++) {
        float2 r0 = *reinterpret_cast<const float2*>(trans + (2 * k)     * CRF_T + c0);
        float2 r1 = *reinterpret_cast<const float2*>(trans + (2 * k + 1) * CRF_T + c0);
        tA[k] = pack2(ex2f(r0.x * LOG2E), ex2f(r1.x * LOG2E));
        tB[k] = pack2(ex2f(r0.y * LOG2E), ex2f(r1.y * LOG2E));
    }

    // ---------------- Init scores ----------------
    const float* ej2 = ebase + c0;
    float  mk0 = mb[0];
    float2 ev0 = *reinterpret_cast<const float2*>(ej2);
    float s0 = ev0.x * mk0;
    float s1 = ev0.y * mk0;

    // exact warp max for the initial reference
    float M0 = fmaxf(s0, s1);
    #pragma unroll
    for (int off = 16; off; off >>= 1)
        M0 = fmaxf(M0, __shfl_xor_sync(0xffffffffu, M0, off));

    if (j == 0) { sMref[wid][0] = s0; sMref[wid][1] = M0; }
    float mref = M0;   // used at iter 1; thereafter lag-2 lane-0 score (exact cancel)

    // 4-deep prefetch over emissions (float2) / mask
    float2 pe2[4];
    float  pm[4];
    #pragma unroll
    for (int p = 0; p < 4; p++) {
        int s = 1 + p;
        pe2[p] = *reinterpret_cast<const float2*>(ej2 + (size_t)s * CRF_T);
        pm[p]  = mb[s];
    }

    #pragma unroll 4
    for (int s = 1; s < CRF_S; s++) {
        const int buf = s & 1;
        const int p   = (s - 1) & 3;
        float2 em = pe2[p];
        float  mk = pm[p];
        int sn = s + 4;
        if (sn < CRF_S) {
            pe2[p] = *reinterpret_cast<const float2*>(ej2 + (size_t)sn * CRF_T);
            pm[p]  = mb[sn];
        }

        // E[c] = exp(score - mref); publish to this row's buffer
        float e0 = ex2f((s0 - mref) * LOG2E);
        float e1 = ex2f((s1 - mref) * LOG2E);
        *reinterpret_cast<float2*>(&sE[wid][buf][c0]) = make_float2(e0, e1);
        __syncwarp();

        // lag-2 reference for iter s+1 (slot (s+1)&1 holds score(s-1))
        float mpf = sMref[wid][(s + 1) & 1];

        // dot: per output column, sum_i E[i]*Texp[i][c]; packed f32x2 MACs
        const float4* E4 = reinterpret_cast<const float4*>(sE[wid][buf]);
        u64 a0 = 0ull, a1 = 0ull, b0 = 0ull, b1 = 0ull;
        #pragma unroll
        for (int k = 0; k < CRF_T / 4; k++) {
            float4 f = E4[k];
            u64 exy = pack2(f.x, f.y);
            u64 ezw = pack2(f.z, f.w);
            a0 = ffma2(exy, tA[2 * k],     a0);
            a1 = ffma2(ezw, tA[2 * k + 1], a1);
            b0 = ffma2(exy, tB[2 * k],     b0);
            b1 = ffma2(ezw, tB[2 * k + 1], b1);
        }
        float xa0, ya0, xa1, ya1, xb0, yb0, xb1, yb1;
        unpack2(a0, xa0, ya0); unpack2(a1, xa1, ya1);
        unpack2(b0, xb0, yb0); unpack2(b1, xb1, yb1);
        float sA = (xa0 + xa1) + (ya0 + ya1);
        float sB = (xb0 + xb1) + (yb0 + yb1);

        s0 = fmaf(lg2f(sA), LN2, mref) + em.x * mk;
        s1 = fmaf(lg2f(sB), LN2, mref) + em.y * mk;

        if (j == 0) sMref[wid][buf] = s0;   // read at iter s+1 -> mref at s+2
        mref = mpf;
    }

    // ---------------- Final logsumexp over 64 states (in-warp) ----------------
    float m = fmaxf(s0, s1);
    #pragma unroll
    for (int off = 16; off; off >>= 1)
        m = fmaxf(m, __shfl_xor_sync(0xffffffffu, m, off));

    float e = ex2f((s0 - m) * LOG2E) + ex2f((s1 - m) * LOG2E);
    #pragma unroll
    for (int off = 16; off; off >>= 1)
        e += __shfl_xor_sync(0xffffffffu, e, off);

    if (j == 0) {
        float fwd = fmaf(lg2f(e), LN2, m);
        g_partial[b] = fwd - g;
    }
}

__global__ __launch_bounds__(CRF_B)
void crf_reduce(float* __restrict__ out)
{
    __shared__ float s[CRF_B];
    int t = threadIdx.x;
    s[t] = g_partial[t];
    __syncthreads();
    #pragma unroll
    for (int off = CRF_B / 2; off > 0; off >>= 1) {
        if (t < off) s[t] += s[t + off];
        __syncthreads();
    }
    if (t == 0) out[0] = s[0] * (1.0f / CRF_B);
}

extern "C" void kernel_launch(void* const* d_in, const int* in_sizes, int n_in,
                              void* d_out, int out_size)
{
    const float* emis  = (const float*)d_in[0];
    const int*   tags  = (const int*)  d_in[1];
    const float* mask  = (const float*)d_in[2];
    const float* trans = (const float*)d_in[3];

    crf_main<<<NUM_CTAS, 32 * ROWS_PER_CTA>>>(emis, tags, mask, trans);
    crf_reduce<<<1, CRF_B>>>((float*)d_out);
}

// round 4
// speedup vs baseline: 1.0085x; 1.0085x over previous
#include <cuda_runtime.h>
#include <cstdint>

#define CRF_B 512
#define CRF_S 1024
#define CRF_T 64
#define PF 8

__device__ float g_partial[CRF_B];
__device__ int   g_count = 0;

typedef unsigned long long u64;

__device__ __forceinline__ float ex2f(float x) {
    float r; asm("ex2.approx.f32 %0, %1;" : "=f"(r) : "f"(x)); return r;
}
__device__ __forceinline__ float lg2f(float x) {
    float r; asm("lg2.approx.f32 %0, %1;" : "=f"(r) : "f"(x)); return r;
}
__device__ __forceinline__ u64 pack2(float lo, float hi) {
    u64 r; asm("mov.b64 %0, {%1, %2};" : "=l"(r) : "f"(lo), "f"(hi)); return r;
}
__device__ __forceinline__ void unpack2(u64 v, float& lo, float& hi) {
    asm("mov.b64 {%0, %1}, %2;" : "=f"(lo), "=f"(hi) : "l"(v));
}
__device__ __forceinline__ u64 ffma2(u64 a, u64 b, u64 c) {
    u64 d; asm("fma.rn.f32x2 %0, %1, %2, %3;" : "=l"(d) : "l"(a), "l"(b), "l"(c));
    return d;
}
__device__ __forceinline__ u64 fadd2(u64 a, u64 b) {
    u64 d; asm("add.rn.f32x2 %0, %1, %2;" : "=l"(d) : "l"(a), "l"(b));
    return d;
}

__global__ __launch_bounds__(CRF_T, 1)
void crf_main(const float* __restrict__ emis,
              const int*   __restrict__ tags,
              const float* __restrict__ mask,
              const float* __restrict__ trans,
              float* __restrict__ out)
{
    const int b    = blockIdx.x;
    const int j    = threadIdx.x;       // state/column index 0..63
    const int lane = j & 31;
    const int wid  = j >> 5;

    __shared__ __align__(16) float sE[2][CRF_T];   // double-buffered exp(score-ref)
    __shared__ float sMref[2];
    __shared__ float sAux[2];
    __shared__ bool  sLast;

    const float LOG2E = 1.4426950408889634f;
    const float LN2   = 0.6931471805599453f;

    const float* mb    = mask + (size_t)b * CRF_S;
    const int*   tb    = tags + (size_t)b * CRF_S;
    const float* ebase = emis + (size_t)b * CRF_S * CRF_T;

    // ---------------- Gold score (gather, split over 64 threads) ------------
    float g = 0.f;
    for (int s = j; s < CRF_S; s += CRF_T) {
        int   tg = tb[s];
        float ev = ebase[(size_t)s * CRF_T + tg];
        float term = (s == 0) ? ev : trans[tg * CRF_T + tb[s - 1]] + ev;
        g += term * mb[s];
    }
    #pragma unroll
    for (int off = 16; off; off >>= 1)
        g += __shfl_xor_sync(0xffffffffu, g, off);
    if (lane == 0) sAux[wid] = g;

    // ---------------- Texp column j -> 32 packed f32x2 registers ------------
    u64 tcp[CRF_T / 2];
    #pragma unroll
    for (int k = 0; k < CRF_T / 2; k++) {
        float a = ex2f(trans[(2 * k)     * CRF_T + j] * LOG2E);
        float c = ex2f(trans[(2 * k + 1) * CRF_T + j] * LOG2E);
        tcp[k] = pack2(a, c);
    }

    const float* ej = ebase + j;
    float score0 = ej[0] * mb[0];
    if (j == 0) sMref[0] = score0;          // ref for iters 1/2 (lane-0 score)
    __syncthreads();                        // also covers sAux for gold
    float gold = sAux[0] + sAux[1];
    float mref      = sMref[0];             // ref_s   (s=1)
    float mref_next = mref;                 // ref_{s+1}

    // E(1) into buffer 1 (iter s reads buf = s&1)
    sE[1][j] = ex2f((score0 - mref) * LOG2E);

    // ---------------- deep register prefetch of emissions/mask --------------
    float pe[PF], pm[PF];
    #pragma unroll
    for (int p = 0; p < PF; p++) {
        int s = 1 + p;
        pe[p] = ej[(size_t)s * CRF_T];
        pm[p] = mb[s];
    }

    #pragma unroll 2
    for (int s = 1; s < CRF_S - 1; s++) {
        const int buf = s & 1;
        const int p   = (s - 1) & (PF - 1);
        float emt = pe[p];
        float mk  = pm[p];
        int sn = s + PF;
        if (sn < CRF_S) { pe[p] = ej[(size_t)sn * CRF_T]; pm[p] = mb[sn]; }

        __syncthreads();                    // orders prev-iter E & ref writes

        float mpf = sMref[(s + 1) & 1];     // lane-0 score from iter s-1

        // exp(delta) computable immediately (off the dot's dependence chain)
        float ed = ex2f((emt * mk + (mref - mref_next)) * LOG2E);

        // dot: P_j = sum_i E_i * Texp[i][j]; operands pre-packed in smem
        const ulonglong2* E2 = reinterpret_cast<const ulonglong2*>(sE[buf]);
        u64 a0 = 0ull, a1 = 0ull, a2 = 0ull, a3 = 0ull;
        #pragma unroll
        for (int k = 0; k < CRF_T / 8; k++) {
            ulonglong2 v0 = E2[2 * k];
            ulonglong2 v1 = E2[2 * k + 1];
            a0 = ffma2(v0.x, tcp[4 * k],     a0);
            a1 = ffma2(v0.y, tcp[4 * k + 1], a1);
            a2 = ffma2(v1.x, tcp[4 * k + 2], a2);
            a3 = ffma2(v1.y, tcp[4 * k + 3], a3);
        }
        u64 t = fadd2(fadd2(a0, a2), fadd2(a1, a3));
        float lo, hi; unpack2(t, lo, hi);
        float P = lo + hi;

        // E(s+1) in linear space: one FMUL on the critical path
        sE[buf ^ 1][j] = P * ed;

        // lane-0 publishes score_s as ref_{s+2} (consumed 2 iters later)
        if (j == 0)
            sMref[buf] = fmaf(lg2f(P), LN2, mref) + emt * mk;

        mref      = mref_next;
        mref_next = mpf;
    }

    // ---------------- peeled last step (s = S-1): need full scores ----------
    {
        const int s   = CRF_S - 1;
        const int buf = s & 1;
        const int p   = (s - 1) & (PF - 1);
        float emt = pe[p];
        float mk  = pm[p];

        __syncthreads();

        const ulonglong2* E2 = reinterpret_cast<const ulonglong2*>(sE[buf]);
        u64 a0 = 0ull, a1 = 0ull, a2 = 0ull, a3 = 0ull;
        #pragma unroll
        for (int k = 0; k < CRF_T / 8; k++) {
            ulonglong2 v0 = E2[2 * k];
            ulonglong2 v1 = E2[2 * k + 1];
            a0 = ffma2(v0.x, tcp[4 * k],     a0);
            a1 = ffma2(v0.y, tcp[4 * k + 1], a1);
            a2 = ffma2(v1.x, tcp[4 * k + 2], a2);
            a3 = ffma2(v1.y, tcp[4 * k + 3], a3);
        }
        u64 t = fadd2(fadd2(a0, a2), fadd2(a1, a3));
        float lo, hi; unpack2(t, lo, hi);
        float P = lo + hi;

        float score = fmaf(lg2f(P), LN2, mref) + emt * mk;

        // ---------------- final logsumexp over 64 states ----------------
        float m = score;
        #pragma unroll
        for (int off = 16; off; off >>= 1)
            m = fmaxf(m, __shfl_xor_sync(0xffffffffu, m, off));
        if (lane == 0) sAux[wid] = m;
        __syncthreads();
        m = fmaxf(sAux[0], sAux[1]);

        float e = ex2f((score - m) * LOG2E);
        #pragma unroll
        for (int off = 16; off; off >>= 1)
            e += __shfl_xor_sync(0xffffffffu, e, off);
        if (lane == 0) sAux[wid] = e;
        __syncthreads();

        if (j == 0) {
            float fwd = fmaf(lg2f(sAux[0] + sAux[1]), LN2, m);
            g_partial[b] = fwd - gold;
        }
    }

    // ---------------- last-arriving block reduces the mean -------------------
    if (j == 0) {
        __threadfence();
        int c = atomicAdd(&g_count, 1);
        sLast = (c == CRF_B - 1);
        if (sLast) g_count = 0;             // reset for graph replay
    }
    __syncthreads();
    if (sLast) {
        __threadfence();
        float v = 0.f;
        #pragma unroll
        for (int i = 0; i < CRF_B / CRF_T; i++)
            v += g_partial[i * CRF_T + j];
        #pragma unroll
        for (int off = 16; off; off >>= 1)
            v += __shfl_xor_sync(0xffffffffu, v, off);
        if (lane == 0) sAux[wid] = v;
        __syncthreads();
        if (j == 0) out[0] = (sAux[0] + sAux[1]) * (1.0f / CRF_B);
    }
}

extern "C" void kernel_launch(void* const* d_in, const int* in_sizes, int n_in,
                              void* d_out, int out_size)
{
    const float* emis  = (const float*)d_in[0];
    const int*   tags  = (const int*)  d_in[1];
    const float* mask  = (const float*)d_in[2];
    const float* trans = (const float*)d_in[3];

    crf_main<<<CRF_B, CRF_T>>>(emis, tags, mask, trans, (float*)d_out);
}

// round 5
// speedup vs baseline: 1.7372x; 1.7225x over previous
#include <cuda_runtime.h>
#include <cstdint>

#define CRF_B 512
#define CRF_S 1024
#define CRF_T 64
#define CHUNK 32
#define NCHUNK (CRF_S / CHUNK)   /* 32 */
#define NBUF 3

__device__ float g_partial[CRF_B];
__device__ int   g_count = 0;

typedef unsigned long long u64;

__device__ __forceinline__ float ex2f(float x) {
    float r; asm("ex2.approx.f32 %0, %1;" : "=f"(r) : "f"(x)); return r;
}
__device__ __forceinline__ float lg2f(float x) {
    float r; asm("lg2.approx.f32 %0, %1;" : "=f"(r) : "f"(x)); return r;
}
__device__ __forceinline__ u64 pack2(float lo, float hi) {
    u64 r; asm("mov.b64 %0, {%1, %2};" : "=l"(r) : "f"(lo), "f"(hi)); return r;
}
__device__ __forceinline__ void unpack2(u64 v, float& lo, float& hi) {
    asm("mov.b64 {%0, %1}, %2;" : "=f"(lo), "=f"(hi) : "l"(v));
}
__device__ __forceinline__ u64 ffma2(u64 a, u64 b, u64 c) {
    u64 d; asm("fma.rn.f32x2 %0, %1, %2, %3;" : "=l"(d) : "l"(a), "l"(b), "l"(c));
    return d;
}
__device__ __forceinline__ u64 fadd2(u64 a, u64 b) {
    u64 d; asm("add.rn.f32x2 %0, %1, %2;" : "=l"(d) : "l"(a), "l"(b));
    return d;
}
__device__ __forceinline__ void cp16(uint32_t dst, const void* src) {
    asm volatile("cp.async.cg.shared.global [%0], [%1], 16;" :: "r"(dst), "l"(src));
}

__global__ __launch_bounds__(CRF_T, 1)
void crf_main(const float* __restrict__ emis,
              const int*   __restrict__ tags,
              const float* __restrict__ mask,
              const float* __restrict__ trans,
              float* __restrict__ out)
{
    const int b    = blockIdx.x;
    const int j    = threadIdx.x;       // state/column index 0..63
    const int lane = j & 31;
    const int wid  = j >> 5;

    __shared__ __align__(16) float sEm[NBUF][CHUNK][CRF_T];  // 24 KB staged emissions
    __shared__ __align__(16) float sMk[NBUF][CHUNK];         // staged mask
    __shared__ __align__(16) float sE[2][CRF_T];             // double-buffered E
    __shared__ float sMref[2];
    __shared__ float sAux[2];
    __shared__ bool  sLast;

    const float LOG2E = 1.4426950408889634f;
    const float LN2   = 0.6931471805599453f;

    const float* mb    = mask + (size_t)b * CRF_S;
    const int*   tb    = tags + (size_t)b * CRF_S;
    const float* ebase = emis + (size_t)b * CRF_S * CRF_T;

    // ---- cp.async chunk issuer (chunk c covers steps [32c, 32c+32)) --------
    auto issue_chunk = [&](int c) {
        const int   cb  = c % NBUF;
        const float* src = ebase + (size_t)c * CHUNK * CRF_T;
        uint32_t d0 = (uint32_t)__cvta_generic_to_shared(&sEm[cb][0][0]);
        #pragma unroll
        for (int k = 0; k < 8; k++) {
            int u = k * CRF_T + j;                   // 0..511 sixteen-byte units
            cp16(d0 + u * 16, src + u * 4);
        }
        if (j < 8) {
            uint32_t dm = (uint32_t)__cvta_generic_to_shared(&sMk[cb][0]);
            cp16(dm + j * 16, mb + c * CHUNK + j * 4);
        }
        asm volatile("cp.async.commit_group;" ::: "memory");
    };

    // Prologue: chunks 0 and 1 in flight before anything else.
    issue_chunk(0);
    issue_chunk(1);

    // ---------------- Gold score (gather, split over 64 threads) ------------
    float g = 0.f;
    for (int s = j; s < CRF_S; s += CRF_T) {
        int   tg = tb[s];
        float ev = ebase[(size_t)s * CRF_T + tg];
        float term = (s == 0) ? ev : trans[tg * CRF_T + tb[s - 1]] + ev;
        g += term * mb[s];
    }
    #pragma unroll
    for (int off = 16; off; off >>= 1)
        g += __shfl_xor_sync(0xffffffffu, g, off);
    if (lane == 0) sAux[wid] = g;

    // ---------------- Texp column j -> 32 packed f32x2 registers ------------
    u64 tcp[CRF_T / 2];
    #pragma unroll
    for (int k = 0; k < CRF_T / 2; k++) {
        float a = ex2f(trans[(2 * k)     * CRF_T + j] * LOG2E);
        float c = ex2f(trans[(2 * k + 1) * CRF_T + j] * LOG2E);
        tcp[k] = pack2(a, c);
    }

    float score0 = ebase[j] * mb[0];
    if (j == 0) sMref[0] = score0;          // ref for s=1,2 (lane-0 score)
    __syncthreads();                        // publishes sAux (gold) + sMref
    float gold = sAux[0] + sAux[1];
    float mref      = sMref[0];             // ref_s   at s=1
    float mref_next = mref;                 // ref_{s+1}

    // E(1) into buffer 1 (iter s reads sE[s&1])
    sE[1][j] = ex2f((score0 - mref) * LOG2E);

    // ================= main recurrence, chunked over staged smem ============
    for (int c = 0; c < NCHUNK; ++c) {
        if (c == NCHUNK - 1) asm volatile("cp.async.wait_group 0;" ::: "memory");
        else                 asm volatile("cp.async.wait_group 1;" ::: "memory");
        __syncthreads();                    // publish chunk c across warps
        if (c + 2 < NCHUNK) issue_chunk(c + 2);

        const int cb   = c % NBUF;
        const int sBeg = (c == 0) ? 1 : c * CHUNK;
        const int sEnd = (c == NCHUNK - 1) ? (CRF_S - 1) : (c + 1) * CHUNK;

        #pragma unroll 4
        for (int s = sBeg; s < sEnd; ++s) {
            __syncthreads();                // orders prev-iter E & ref writes

            float mpf = sMref[(s + 1) & 1]; // lane-0 score from iter s-1
            float emt = sEm[cb][s & (CHUNK - 1)][j];
            float mk  = sMk[cb][s & (CHUNK - 1)];

            // off-critical-path rescale factor
            float ed = ex2f((emt * mk + (mref - mref_next)) * LOG2E);

            // dot: P_j = sum_i E_i * Texp[i][j]
            const ulonglong2* E2 = reinterpret_cast<const ulonglong2*>(sE[s & 1]);
            u64 a0 = 0ull, a1 = 0ull, a2 = 0ull, a3 = 0ull;
            #pragma unroll
            for (int k = 0; k < CRF_T / 8; k++) {
                ulonglong2 v0 = E2[2 * k];
                ulonglong2 v1 = E2[2 * k + 1];
                a0 = ffma2(v0.x, tcp[4 * k],     a0);
                a1 = ffma2(v0.y, tcp[4 * k + 1], a1);
                a2 = ffma2(v1.x, tcp[4 * k + 2], a2);
                a3 = ffma2(v1.y, tcp[4 * k + 3], a3);
            }
            u64 t = fadd2(fadd2(a0, a2), fadd2(a1, a3));
            float lo, hi; unpack2(t, lo, hi);
            float P = lo + hi;

            // E(s+1) in linear space: one FMUL on the critical path
            sE[(s & 1) ^ 1][j] = P * ed;

            // lane-0 publishes score_s as ref_{s+2}
            if (j == 0)
                sMref[s & 1] = fmaf(lg2f(P), LN2, mref) + emt * mk;

            mref      = mref_next;
            mref_next = mpf;
        }
    }

    // ---------------- peeled last step (s = S-1): need full scores ----------
    {
        const int s  = CRF_S - 1;
        const int cb = (NCHUNK - 1) % NBUF;
        float emt = sEm[cb][s & (CHUNK - 1)][j];
        float mk  = sMk[cb][s & (CHUNK - 1)];

        __syncthreads();

        const ulonglong2* E2 = reinterpret_cast<const ulonglong2*>(sE[s & 1]);
        u64 a0 = 0ull, a1 = 0ull, a2 = 0ull, a3 = 0ull;
        #pragma unroll
        for (int k = 0; k < CRF_T / 8; k++) {
            ulonglong2 v0 = E2[2 * k];
            ulonglong2 v1 = E2[2 * k + 1];
            a0 = ffma2(v0.x, tcp[4 * k],     a0);
            a1 = ffma2(v0.y, tcp[4 * k + 1], a1);
            a2 = ffma2(v1.x, tcp[4 * k + 2], a2);
            a3 = ffma2(v1.y, tcp[4 * k + 3], a3);
        }
        u64 t = fadd2(fadd2(a0, a2), fadd2(a1, a3));
        float lo, hi; unpack2(t, lo, hi);
        float P = lo + hi;

        float score = fmaf(lg2f(P), LN2, mref) + emt * mk;

        // ---------------- final logsumexp over 64 states ----------------
        float m = score;
        #pragma unroll
        for (int off = 16; off; off >>= 1)
            m = fmaxf(m, __shfl_xor_sync(0xffffffffu, m, off));
        if (lane == 0) sAux[wid] = m;
        __syncthreads();
        m = fmaxf(sAux[0], sAux[1]);

        float e = ex2f((score - m) * LOG2E);
        #pragma unroll
        for (int off = 16; off; off >>= 1)
            e += __shfl_xor_sync(0xffffffffu, e, off);
        if (lane == 0) sAux[wid] = e;
        __syncthreads();

        if (j == 0) {
            float fwd = fmaf(lg2f(sAux[0] + sAux[1]), LN2, m);
            g_partial[b] = fwd - gold;
        }
    }

    // ---------------- last-arriving block reduces the mean -------------------
    if (j == 0) {
        __threadfence();
        int c = atomicAdd(&g_count, 1);
        sLast = (c == CRF_B - 1);
        if (sLast) g_count = 0;             // reset for graph replay
    }
    __syncthreads();
    if (sLast) {
        __threadfence();
        float v = 0.f;
        #pragma unroll
        for (int i = 0; i < CRF_B / CRF_T; i++)
            v += g_partial[i * CRF_T + j];
        #pragma unroll
        for (int off = 16; off; off >>= 1)
            v += __shfl_xor_sync(0xffffffffu, v, off);
        if (lane == 0) sAux[wid] = v;
        __syncthreads();
        if (j == 0) out[0] = (sAux[0] + sAux[1]) * (1.0f / CRF_B);
    }
}

extern "C" void kernel_launch(void* const* d_in, const int* in_sizes, int n_in,
                              void* d_out, int out_size)
{
    const float* emis  = (const float*)d_in[0];
    const int*   tags  = (const int*)  d_in[1];
    const float* mask  = (const float*)d_in[2];
    const float* trans = (const float*)d_in[3];

    crf_main<<<CRF_B, CRF_T>>>(emis, tags, mask, trans, (float*)d_out);
}

// round 6
// speedup vs baseline: 2.0089x; 1.1564x over previous
#include <cuda_runtime.h>
#include <cstdint>

#define CRF_B 512
#define CRF_S 1024
#define CRF_T 64
#define CHUNK 32
#define NCHUNK (CRF_S / CHUNK)
#define NBUF 3

__device__ float g_partial[CRF_B];
__device__ int   g_count = 0;

typedef unsigned long long u64;

__device__ __forceinline__ float ex2f(float x) {
    float r; asm("ex2.approx.f32 %0, %1;" : "=f"(r) : "f"(x)); return r;
}
__device__ __forceinline__ float lg2f(float x) {
    float r; asm("lg2.approx.f32 %0, %1;" : "=f"(r) : "f"(x)); return r;
}
__device__ __forceinline__ u64 pack2(float lo, float hi) {
    u64 r; asm("mov.b64 %0, {%1, %2};" : "=l"(r) : "f"(lo), "f"(hi)); return r;
}
__device__ __forceinline__ void unpack2(u64 v, float& lo, float& hi) {
    asm("mov.b64 {%0, %1}, %2;" : "=f"(lo), "=f"(hi) : "l"(v));
}
__device__ __forceinline__ u64 ffma2(u64 a, u64 b, u64 c) {
    u64 d; asm("fma.rn.f32x2 %0, %1, %2, %3;" : "=l"(d) : "l"(a), "l"(b), "l"(c));
    return d;
}
__device__ __forceinline__ u64 fadd2(u64 a, u64 b) {
    u64 d; asm("add.rn.f32x2 %0, %1, %2;" : "=l"(d) : "l"(a), "l"(b));
    return d;
}
__device__ __forceinline__ void cp16(uint32_t dst, const void* src) {
    asm volatile("cp.async.cg.shared.global [%0], [%1], 16;" :: "r"(dst), "l"(src));
}

__global__ __launch_bounds__(32, 1)
void crf_main(const float* __restrict__ emis,
              const int*   __restrict__ tags,
              const float* __restrict__ mask,
              const float* __restrict__ trans,
              float* __restrict__ out)
{
    const int b = blockIdx.x;
    const int l = threadIdx.x;          // lane; owns columns 2l, 2l+1
    const int c0 = 2 * l;

    __shared__ __align__(16) float sEm[NBUF][CHUNK][CRF_T];  // 24 KB staged emissions
    __shared__ __align__(16) float sMk[NBUF][CHUNK];
    __shared__ __align__(16) float sE[2][CRF_T];             // double-buffered E
    __shared__ float sMref[2];

    const float LOG2E = 1.4426950408889634f;
    const float LN2   = 0.6931471805599453f;

    const float* mb    = mask + (size_t)b * CRF_S;
    const int*   tb    = tags + (size_t)b * CRF_S;
    const float* ebase = emis + (size_t)b * CRF_S * CRF_T;

    // ---- cp.async chunk issuer (chunk c covers steps [32c, 32c+32)) --------
    auto issue_chunk = [&](int c) {
        const int    cb  = c % NBUF;
        const float* src = ebase + (size_t)c * CHUNK * CRF_T;
        uint32_t d0 = (uint32_t)__cvta_generic_to_shared(&sEm[cb][0][0]);
        #pragma unroll
        for (int k = 0; k < 16; k++) {
            int u = k * 32 + l;                    // 512 sixteen-byte units
            cp16(d0 + u * 16, src + u * 4);
        }
        if (l < 8) {
            uint32_t dm = (uint32_t)__cvta_generic_to_shared(&sMk[cb][0]);
            cp16(dm + l * 16, mb + c * CHUNK + l * 4);
        }
        asm volatile("cp.async.commit_group;" ::: "memory");
    };

    issue_chunk(0);
    issue_chunk(1);

    // ---------------- Gold score (gather, 32 lanes) -------------------------
    float g = 0.f;
    for (int s = l; s < CRF_S; s += 32) {
        int   tg = tb[s];
        float ev = ebase[(size_t)s * CRF_T + tg];
        float term = (s == 0) ? ev : trans[tg * CRF_T + tb[s - 1]] + ev;
        g += term * mb[s];
    }
    #pragma unroll
    for (int off = 16; off; off >>= 1)
        g += __shfl_xor_sync(0xffffffffu, g, off);

    // -------- Texp columns c0, c0+1 as i-pair-packed f32x2 (64 u64 regs) ----
    // tA[k] = (T[2k][c0],   T[2k+1][c0])   exp'd
    // tB[k] = (T[2k][c0+1], T[2k+1][c0+1]) exp'd
    u64 tA[CRF_T / 2], tB[CRF_T / 2];
    #pragma unroll
    for (int k = 0; k < CRF_T / 2; k++) {
        float2 r0 = *reinterpret_cast<const float2*>(trans + (2 * k)     * CRF_T + c0);
        float2 r1 = *reinterpret_cast<const float2*>(trans + (2 * k + 1) * CRF_T + c0);
        tA[k] = pack2(ex2f(r0.x * LOG2E), ex2f(r1.x * LOG2E));
        tB[k] = pack2(ex2f(r0.y * LOG2E), ex2f(r1.y * LOG2E));
    }

    // ---------------- init ----------------
    float  mk0 = mb[0];
    float2 ev0 = *reinterpret_cast<const float2*>(ebase + c0);
    float s0 = ev0.x * mk0;
    float s1 = ev0.y * mk0;
    float mref = __shfl_sync(0xffffffffu, s0, 0);   // lane-0 col-0 score as ref
    if (l == 0) sMref[0] = s0;
    float mref_next = mref;

    // E(1) into buffer 1
    *reinterpret_cast<float2*>(&sE[1][c0]) =
        make_float2(ex2f((s0 - mref) * LOG2E), ex2f((s1 - mref) * LOG2E));

    // ================= main recurrence =================
    for (int c = 0; c < NCHUNK; ++c) {
        if (c == NCHUNK - 1) asm volatile("cp.async.wait_group 0;" ::: "memory");
        else                 asm volatile("cp.async.wait_group 1;" ::: "memory");
        __syncwarp();
        if (c + 2 < NCHUNK) issue_chunk(c + 2);

        const int cb   = c % NBUF;
        const int sBeg = (c == 0) ? 1 : c * CHUNK;
        const int sEnd = (c == NCHUNK - 1) ? (CRF_S - 1) : (c + 1) * CHUNK;

        #pragma unroll 4
        for (int s = sBeg; s < sEnd; ++s) {
            __syncwarp();                   // orders prev-iter E & ref writes

            float  mpf = sMref[(s + 1) & 1];
            float2 em  = *reinterpret_cast<const float2*>(&sEm[cb][s & (CHUNK - 1)][c0]);
            float  mk  = sMk[cb][s & (CHUNK - 1)];

            // off-critical-path rescale factors (per column)
            float dref = mref - mref_next;
            float ed0 = ex2f((em.x * mk + dref) * LOG2E);
            float ed1 = ex2f((em.y * mk + dref) * LOG2E);

            // dot for both columns; E read as pre-packed i-pairs
            const ulonglong2* E2 = reinterpret_cast<const ulonglong2*>(sE[s & 1]);
            u64 a0 = 0ull, a1 = 0ull, b0 = 0ull, b1 = 0ull;
            #pragma unroll
            for (int k = 0; k < CRF_T / 4; k++) {
                ulonglong2 v = E2[k];       // i-pairs (4k..4k+1), (4k+2..4k+3)
                a0 = ffma2(v.x, tA[2 * k],     a0);
                a1 = ffma2(v.y, tA[2 * k + 1], a1);
                b0 = ffma2(v.x, tB[2 * k],     b0);
                b1 = ffma2(v.y, tB[2 * k + 1], b1);
            }
            u64 ta = fadd2(a0, a1);
            u64 tb2 = fadd2(b0, b1);
            float xa, ya, xb, yb;
            unpack2(ta, xa, ya); unpack2(tb2, xb, yb);
            float P0 = xa + ya;
            float P1 = xb + yb;

            // E(s+1) in linear space
            *reinterpret_cast<float2*>(&sE[(s & 1) ^ 1][c0]) =
                make_float2(P0 * ed0, P1 * ed1);

            // lane-0 publishes score_s (col 0) as ref_{s+2}
            if (l == 0)
                sMref[s & 1] = fmaf(lg2f(P0), LN2, mref) + em.x * mk;

            mref      = mref_next;
            mref_next = mpf;
        }
    }

    // ---------------- peeled last step (s = S-1) ----------------
    {
        const int s  = CRF_S - 1;
        const int cb = (NCHUNK - 1) % NBUF;
        float2 em = *reinterpret_cast<const float2*>(&sEm[cb][s & (CHUNK - 1)][c0]);
        float  mk = sMk[cb][s & (CHUNK - 1)];

        __syncwarp();

        const ulonglong2* E2 = reinterpret_cast<const ulonglong2*>(sE[s & 1]);
        u64 a0 = 0ull, a1 = 0ull, b0 = 0ull, b1 = 0ull;
        #pragma unroll
        for (int k = 0; k < CRF_T / 4; k++) {
            ulonglong2 v = E2[k];
            a0 = ffma2(v.x, tA[2 * k],     a0);
            a1 = ffma2(v.y, tA[2 * k + 1], a1);
            b0 = ffma2(v.x, tB[2 * k],     b0);
            b1 = ffma2(v.y, tB[2 * k + 1], b1);
        }
        u64 ta = fadd2(a0, a1);
        u64 tb2 = fadd2(b0, b1);
        float xa, ya, xb, yb;
        unpack2(ta, xa, ya); unpack2(tb2, xb, yb);

        float sc0 = fmaf(lg2f(xa + ya), LN2, mref) + em.x * mk;
        float sc1 = fmaf(lg2f(xb + yb), LN2, mref) + em.y * mk;

        // final logsumexp over 64 states, in-warp
        float m = fmaxf(sc0, sc1);
        #pragma unroll
        for (int off = 16; off; off >>= 1)
            m = fmaxf(m, __shfl_xor_sync(0xffffffffu, m, off));

        float e = ex2f((sc0 - m) * LOG2E) + ex2f((sc1 - m) * LOG2E);
        #pragma unroll
        for (int off = 16; off; off >>= 1)
            e += __shfl_xor_sync(0xffffffffu, e, off);

        if (l == 0) {
            float fwd = fmaf(lg2f(e), LN2, m);
            g_partial[b] = fwd - g;
        }
    }

    // ---------------- last-arriving block reduces the mean -------------------
    bool last = false;
    if (l == 0) {
        __threadfence();
        int c = atomicAdd(&g_count, 1);
        last = (c == CRF_B - 1);
        if (last) g_count = 0;              // reset for graph replay
    }
    last = __shfl_sync(0xffffffffu, last, 0);
    if (last) {
        __threadfence();
        float v = 0.f;
        #pragma unroll
        for (int i = 0; i < CRF_B / 32; i++)
            v += g_partial[i * 32 + l];
        #pragma unroll
        for (int off = 16; off; off >>= 1)
            v += __shfl_xor_sync(0xffffffffu, v, off);
        if (l == 0) out[0] = v * (1.0f / CRF_B);
    }
}

extern "C" void kernel_launch(void* const* d_in, const int* in_sizes, int n_in,
                              void* d_out, int out_size)
{
    const float* emis  = (const float*)d_in[0];
    const int*   tags  = (const int*)  d_in[1];
    const float* mask  = (const float*)d_in[2];
    const float* trans = (const float*)d_in[3];

    crf_main<<<CRF_B, 32>>>(emis, tags, mask, trans, (float*)d_out);
}

// round 7
// speedup vs baseline: 2.1263x; 1.0585x over previous
#include <cuda_runtime.h>
#include <cstdint>

#define CRF_B 512
#define CRF_S 1024
#define CRF_T 64
#define CHUNK 32
#define NCHUNK (CRF_S / CHUNK)
#define NBUF 2

__device__ float g_partial[CRF_B];
__device__ int   g_count = 0;

typedef unsigned long long u64;

__device__ __forceinline__ float ex2f(float x) {
    float r; asm("ex2.approx.f32 %0, %1;" : "=f"(r) : "f"(x)); return r;
}
__device__ __forceinline__ float lg2f(float x) {
    float r; asm("lg2.approx.f32 %0, %1;" : "=f"(r) : "f"(x)); return r;
}
__device__ __forceinline__ u64 pack2(float lo, float hi) {
    u64 r; asm("mov.b64 %0, {%1, %2};" : "=l"(r) : "f"(lo), "f"(hi)); return r;
}
__device__ __forceinline__ void unpack2(u64 v, float& lo, float& hi) {
    asm("mov.b64 {%0, %1}, %2;" : "=f"(lo), "=f"(hi) : "l"(v));
}
__device__ __forceinline__ u64 ffma2(u64 a, u64 b, u64 c) {
    u64 d; asm("fma.rn.f32x2 %0, %1, %2, %3;" : "=l"(d) : "l"(a), "l"(b), "l"(c));
    return d;
}
__device__ __forceinline__ u64 fadd2(u64 a, u64 b) {
    u64 d; asm("add.rn.f32x2 %0, %1, %2;" : "=l"(d) : "l"(a), "l"(b));
    return d;
}
__device__ __forceinline__ void cp16(uint32_t dst, const void* src) {
    asm volatile("cp.async.cg.shared.global [%0], [%1], 16;" :: "r"(dst), "l"(src));
}

__global__ __launch_bounds__(32, 1)
void crf_main(const float* __restrict__ emis,
              const int*   __restrict__ tags,
              const float* __restrict__ mask,
              const float* __restrict__ trans,
              float* __restrict__ out)
{
    const int b  = blockIdx.x;
    const int l  = threadIdx.x;         // lane; owns columns 2l, 2l+1
    const int c0 = 2 * l;

    __shared__ __align__(16) float sEm[NBUF][CHUNK][CRF_T];  // 16 KB emissions
    __shared__ __align__(16) float sMk[NBUF][CHUNK];         // mask
    __shared__ __align__(16) int   sTg[NBUF][CHUNK];         // tags
    __shared__ __align__(16) float sE[2][CRF_T];             // double-buffered E
    __shared__ float sMref[2];

    const float LOG2E = 1.4426950408889634f;
    const float LN2   = 0.6931471805599453f;

    const float* mb    = mask + (size_t)b * CRF_S;
    const int*   tb    = tags + (size_t)b * CRF_S;
    const float* ebase = emis + (size_t)b * CRF_S * CRF_T;

    // ---- cp.async chunk issuer: emissions + mask + tags for chunk c --------
    auto issue_chunk = [&](int c) {
        const int    cb  = c & 1;
        const float* src = ebase + (size_t)c * CHUNK * CRF_T;
        uint32_t d0 = (uint32_t)__cvta_generic_to_shared(&sEm[cb][0][0]);
        #pragma unroll
        for (int k = 0; k < 16; k++) {
            int u = k * 32 + l;                    // 512 sixteen-byte units
            cp16(d0 + u * 16, src + u * 4);
        }
        if (l < 8) {
            uint32_t dm = (uint32_t)__cvta_generic_to_shared(&sMk[cb][0]);
            cp16(dm + l * 16, mb + c * CHUNK + l * 4);
        } else if (l < 16) {
            uint32_t dt = (uint32_t)__cvta_generic_to_shared(&sTg[cb][0]);
            cp16(dt + (l - 8) * 16, tb + c * CHUNK + (l - 8) * 4);
        }
        asm volatile("cp.async.commit_group;" ::: "memory");
    };

    issue_chunk(0);
    issue_chunk(1);

    // -------- Texp columns c0, c0+1 as i-pair-packed f32x2 (64 u64 regs) ----
    u64 tA[CRF_T / 2], tB[CRF_T / 2];
    #pragma unroll
    for (int k = 0; k < CRF_T / 2; k++) {
        float2 r0 = *reinterpret_cast<const float2*>(trans + (2 * k)     * CRF_T + c0);
        float2 r1 = *reinterpret_cast<const float2*>(trans + (2 * k + 1) * CRF_T + c0);
        tA[k] = pack2(ex2f(r0.x * LOG2E), ex2f(r1.x * LOG2E));
        tB[k] = pack2(ex2f(r0.y * LOG2E), ex2f(r1.y * LOG2E));
    }

    // ---------------- init (step 0) ----------------
    float  mk0 = mb[0];
    float2 ev0 = *reinterpret_cast<const float2*>(ebase + c0);
    float s0 = ev0.x * mk0;
    float s1 = ev0.y * mk0;
    float mref = __shfl_sync(0xffffffffu, s0, 0);   // lane-0 col-0 score as ref
    if (l == 0) sMref[0] = s0;
    float mref_next = mref;

    // gold: step-0 term; rest interleaved into the main loop (all lanes redundant)
    int   tgp = tb[0];
    float g   = ebase[tgp] * mk0;

    // E(1) into buffer 1
    *reinterpret_cast<float2*>(&sE[1][c0]) =
        make_float2(ex2f((s0 - mref) * LOG2E), ex2f((s1 - mref) * LOG2E));

    // ================= main recurrence =================
    for (int c = 0; c < NCHUNK; ++c) {
        if (c >= NCHUNK - 2) asm volatile("cp.async.wait_group 0;" ::: "memory");
        else                 asm volatile("cp.async.wait_group 1;" ::: "memory");
        __syncwarp();

        const int cb   = c & 1;
        const int sBeg = (c == 0) ? 1 : c * CHUNK;
        const int sEnd = (c == NCHUNK - 1) ? (CRF_S - 1) : (c + 1) * CHUNK;

        #pragma unroll 8
        for (int s = sBeg; s < sEnd; ++s) {
            __syncwarp();                   // orders prev-iter E & ref writes

            const int idx = s & (CHUNK - 1);
            float  mpf = sMref[(s + 1) & 1];
            float2 em  = *reinterpret_cast<const float2*>(&sEm[cb][idx][c0]);
            float  mk  = sMk[cb][idx];

            // ---- interleaved gold step (uniform across lanes, off-path) ----
            int   tg  = sTg[cb][idx];
            float ge  = sEm[cb][idx][tg];
            float gt  = __ldg(trans + tg * CRF_T + tgp);
            g  = fmaf(gt + ge, mk, g);
            tgp = tg;

            // ---- off-critical-path rescale factors (per column) ----
            float mkl   = mk * LOG2E;
            float dref2 = (mref - mref_next) * LOG2E;
            float ed0 = ex2f(fmaf(em.x, mkl, dref2));
            float ed1 = ex2f(fmaf(em.y, mkl, dref2));

            // ---- dot for both columns; E read as pre-packed i-pairs ----
            const ulonglong2* E2 = reinterpret_cast<const ulonglong2*>(sE[s & 1]);
            u64 a0 = 0ull, a1 = 0ull, b0 = 0ull, b1 = 0ull;
            #pragma unroll
            for (int k = 0; k < CRF_T / 4; k++) {
                ulonglong2 v = E2[k];
                a0 = ffma2(v.x, tA[2 * k],     a0);
                a1 = ffma2(v.y, tA[2 * k + 1], a1);
                b0 = ffma2(v.x, tB[2 * k],     b0);
                b1 = ffma2(v.y, tB[2 * k + 1], b1);
            }
            u64 ta  = fadd2(a0, a1);
            u64 tb2 = fadd2(b0, b1);
            float xa, ya, xb, yb;
            unpack2(ta, xa, ya); unpack2(tb2, xb, yb);
            float P0 = xa + ya;
            float P1 = xb + yb;

            // E(s+1) in linear space
            *reinterpret_cast<float2*>(&sE[(s & 1) ^ 1][c0]) =
                make_float2(P0 * ed0, P1 * ed1);

            // lane-0 publishes score_s (col 0) as ref_{s+2}
            if (l == 0)
                sMref[s & 1] = fmaf(lg2f(P0), LN2, mref) + em.x * mk;

            mref      = mref_next;
            mref_next = mpf;
        }

        if (c + 2 < NCHUNK) issue_chunk(c + 2);
    }

    // ---------------- peeled last step (s = S-1) ----------------
    {
        const int s   = CRF_S - 1;
        const int cb  = (NCHUNK - 1) & 1;
        const int idx = s & (CHUNK - 1);
        float2 em = *reinterpret_cast<const float2*>(&sEm[cb][idx][c0]);
        float  mk = sMk[cb][idx];

        // gold final term
        int   tg = sTg[cb][idx];
        float ge = sEm[cb][idx][tg];
        float gt = __ldg(trans + tg * CRF_T + tgp);
        g = fmaf(gt + ge, mk, g);

        __syncwarp();

        const ulonglong2* E2 = reinterpret_cast<const ulonglong2*>(sE[s & 1]);
        u64 a0 = 0ull, a1 = 0ull, b0 = 0ull, b1 = 0ull;
        #pragma unroll
        for (int k = 0; k < CRF_T / 4; k++) {
            ulonglong2 v = E2[k];
            a0 = ffma2(v.x, tA[2 * k],     a0);
            a1 = ffma2(v.y, tA[2 * k + 1], a1);
            b0 = ffma2(v.x, tB[2 * k],     b0);
            b1 = ffma2(v.y, tB[2 * k + 1], b1);
        }
        u64 ta  = fadd2(a0, a1);
        u64 tb2 = fadd2(b0, b1);
        float xa, ya, xb, yb;
        unpack2(ta, xa, ya); unpack2(tb2, xb, yb);

        float sc0 = fmaf(lg2f(xa + ya), LN2, mref) + em.x * mk;
        float sc1 = fmaf(lg2f(xb + yb), LN2, mref) + em.y * mk;

        // final logsumexp over 64 states, in-warp
        float m = fmaxf(sc0, sc1);
        #pragma unroll
        for (int off = 16; off; off >>= 1)
            m = fmaxf(m, __shfl_xor_sync(0xffffffffu, m, off));

        float e = ex2f((sc0 - m) * LOG2E) + ex2f((sc1 - m) * LOG2E);
        #pragma unroll
        for (int off = 16; off; off >>= 1)
            e += __shfl_xor_sync(0xffffffffu, e, off);

        if (l == 0) {
            float fwd = fmaf(lg2f(e), LN2, m);
            g_partial[b] = fwd - g;
        }
    }

    // ---------------- last-arriving block reduces the mean -------------------
    bool last = false;
    if (l == 0) {
        __threadfence();
        int c = atomicAdd(&g_count, 1);
        last = (c == CRF_B - 1);
        if (last) g_count = 0;              // reset for graph replay
    }
    last = __shfl_sync(0xffffffffu, last, 0);
    if (last) {
        __threadfence();
        float v = 0.f;
        #pragma unroll
        for (int i = 0; i < CRF_B / 32; i++)
            v += g_partial[i * 32 + l];
        #pragma unroll
        for (int off = 16; off; off >>= 1)
            v += __shfl_xor_sync(0xffffffffu, v, off);
        if (l == 0) out[0] = v * (1.0f / CRF_B);
    }
}

extern "C" void kernel_launch(void* const* d_in, const int* in_sizes, int n_in,
                              void* d_out, int out_size)
{
    const float* emis  = (const float*)d_in[0];
    const int*   tags  = (const int*)  d_in[1];
    const float* mask  = (const float*)d_in[2];
    const float* trans = (const float*)d_in[3];

    crf_main<<<CRF_B, 32>>>(emis, tags, mask, trans, (float*)d_out);
}

// round 8
// speedup vs baseline: 2.2053x; 1.0371x over previous
#include <cuda_runtime.h>
#include <cstdint>

#define CRF_B 512
#define CRF_S 1024
#define CRF_T 64
#define CHUNK 32
#define NCHUNK (CRF_S / CHUNK)
#define NBUF 2

__device__ float g_partial[CRF_B];
__device__ int   g_count = 0;

typedef unsigned long long u64;

__device__ __forceinline__ float ex2f(float x) {
    float r; asm("ex2.approx.f32 %0, %1;" : "=f"(r) : "f"(x)); return r;
}
__device__ __forceinline__ float lg2f(float x) {
    float r; asm("lg2.approx.f32 %0, %1;" : "=f"(r) : "f"(x)); return r;
}
__device__ __forceinline__ u64 pack2(float lo, float hi) {
    u64 r; asm("mov.b64 %0, {%1, %2};" : "=l"(r) : "f"(lo), "f"(hi)); return r;
}
__device__ __forceinline__ void unpack2(u64 v, float& lo, float& hi) {
    asm("mov.b64 {%0, %1}, %2;" : "=f"(lo), "=f"(hi) : "l"(v));
}
__device__ __forceinline__ u64 ffma2(u64 a, u64 b, u64 c) {
    u64 d; asm("fma.rn.f32x2 %0, %1, %2, %3;" : "=l"(d) : "l"(a), "l"(b), "l"(c));
    return d;
}
__device__ __forceinline__ u64 fadd2(u64 a, u64 b) {
    u64 d; asm("add.rn.f32x2 %0, %1, %2;" : "=l"(d) : "l"(a), "l"(b));
    return d;
}
__device__ __forceinline__ void cp16(uint32_t dst, const void* src) {
    asm volatile("cp.async.cg.shared.global [%0], [%1], 16;" :: "r"(dst), "l"(src));
}

__global__ __launch_bounds__(32, 1)
void crf_main(const float* __restrict__ emis,
              const int*   __restrict__ tags,
              const float* __restrict__ mask,
              const float* __restrict__ trans,
              float* __restrict__ out)
{
    const int b  = blockIdx.x;
    const int l  = threadIdx.x;         // lane; owns columns 2l, 2l+1
    const int c0 = 2 * l;

    __shared__ __align__(16) float sEm[NBUF][CHUNK][CRF_T];  // 16 KB emissions
    __shared__ __align__(16) float sMk[NBUF][CHUNK];         // mask
    __shared__ __align__(16) int   sTg[NBUF][CHUNK];         // tags
    __shared__ __align__(16) float sE[2][CRF_T];             // double-buffered E

    const float LOG2E = 1.4426950408889634f;
    const float LN2   = 0.6931471805599453f;

    const float* mb    = mask + (size_t)b * CRF_S;
    const int*   tb    = tags + (size_t)b * CRF_S;
    const float* ebase = emis + (size_t)b * CRF_S * CRF_T;

    // ---- cp.async chunk issuer: emissions + mask + tags for chunk c --------
    auto issue_chunk = [&](int c) {
        const int    cb  = c & 1;
        const float* src = ebase + (size_t)c * CHUNK * CRF_T;
        uint32_t d0 = (uint32_t)__cvta_generic_to_shared(&sEm[cb][0][0]);
        #pragma unroll
        for (int k = 0; k < 16; k++) {
            int u = k * 32 + l;                    // 512 sixteen-byte units
            cp16(d0 + u * 16, src + u * 4);
        }
        if (l < 8) {
            uint32_t dm = (uint32_t)__cvta_generic_to_shared(&sMk[cb][0]);
            cp16(dm + l * 16, mb + c * CHUNK + l * 4);
        } else if (l < 16) {
            uint32_t dt = (uint32_t)__cvta_generic_to_shared(&sTg[cb][0]);
            cp16(dt + (l - 8) * 16, tb + c * CHUNK + (l - 8) * 4);
        }
        asm volatile("cp.async.commit_group;" ::: "memory");
    };

    issue_chunk(0);
    issue_chunk(1);

    // -------- Texp columns c0, c0+1 as i-pair-packed f32x2 (64 u64 regs) ----
    u64 tA[CRF_T / 2], tB[CRF_T / 2];
    #pragma unroll
    for (int k = 0; k < CRF_T / 2; k++) {
        float2 r0 = *reinterpret_cast<const float2*>(trans + (2 * k)     * CRF_T + c0);
        float2 r1 = *reinterpret_cast<const float2*>(trans + (2 * k + 1) * CRF_T + c0);
        tA[k] = pack2(ex2f(r0.x * LOG2E), ex2f(r1.x * LOG2E));
        tB[k] = pack2(ex2f(r0.y * LOG2E), ex2f(r1.y * LOG2E));
    }

    // ---------------- init (step 0) ----------------
    float  mk0 = mb[0];
    float2 ev0 = *reinterpret_cast<const float2*>(ebase + c0);
    float s0 = ev0.x * mk0;
    float s1 = ev0.y * mk0;

    // reference chain, all in registers (every lane tracks it redundantly)
    float mref       = __shfl_sync(0xffffffffu, s0, 0);  // ref_s at s=1
    float mref_next  = mref;                             // ref_{s+1}
    float prev_score = mref;                             // score_{s-1} (col 0)

    // gold: step-0 term; rest interleaved into the main loop
    int   tgp = tb[0];
    float g   = ebase[tgp] * mk0;

    // E(1) into buffer 1
    *reinterpret_cast<float2*>(&sE[1][c0]) =
        make_float2(ex2f((s0 - mref) * LOG2E), ex2f((s1 - mref) * LOG2E));

    // ================= main recurrence =================
    for (int c = 0; c < NCHUNK; ++c) {
        if (c >= NCHUNK - 2) asm volatile("cp.async.wait_group 0;" ::: "memory");
        else                 asm volatile("cp.async.wait_group 1;" ::: "memory");
        __syncwarp();

        const int cb   = c & 1;
        const int sBeg = (c == 0) ? 1 : c * CHUNK;
        const int sEnd = (c == NCHUNK - 1) ? (CRF_S - 1) : (c + 1) * CHUNK;

        #pragma unroll 8
        for (int s = sBeg; s < sEnd; ++s) {
            __syncwarp();                   // orders prev-iter E writes (RAW+WAR)

            const int idx = s & (CHUNK - 1);
            float  mpf = prev_score;        // score_{s-1} (col 0), register
            float2 em  = *reinterpret_cast<const float2*>(&sEm[cb][idx][c0]);
            float  mk  = sMk[cb][idx];
            float  em0 = sEm[cb][idx][0];   // col-0 emission (broadcast LDS)

            // ---- interleaved gold step (uniform across lanes, off-path) ----
            int   tg  = sTg[cb][idx];
            float ge  = sEm[cb][idx][tg];
            float gt  = __ldg(trans + tg * CRF_T + tgp);
            g   = fmaf(gt + ge, mk, g);
            tgp = tg;

            // ---- off-critical-path rescale factors (per column) ----
            float mkl   = mk * LOG2E;
            float dref2 = (mref - mref_next) * LOG2E;
            float ed0 = ex2f(fmaf(em.x, mkl, dref2));
            float ed1 = ex2f(fmaf(em.y, mkl, dref2));

            // ---- dot for both columns; E read as pre-packed i-pairs ----
            const ulonglong2* E2 = reinterpret_cast<const ulonglong2*>(sE[s & 1]);
            u64 a0 = 0ull, a1 = 0ull, b0 = 0ull, b1 = 0ull;
            #pragma unroll
            for (int k = 0; k < CRF_T / 4; k++) {
                ulonglong2 v = E2[k];
                a0 = ffma2(v.x, tA[2 * k],     a0);
                a1 = ffma2(v.y, tA[2 * k + 1], a1);
                b0 = ffma2(v.x, tB[2 * k],     b0);
                b1 = ffma2(v.y, tB[2 * k + 1], b1);
            }
            u64 ta  = fadd2(a0, a1);
            u64 tb2 = fadd2(b0, b1);
            float xa, ya, xb, yb;
            unpack2(ta, xa, ya); unpack2(tb2, xb, yb);
            float P0 = xa + ya;
            float P1 = xb + yb;

            // E(s+1) in linear space
            *reinterpret_cast<float2*>(&sE[(s & 1) ^ 1][c0]) =
                make_float2(P0 * ed0, P1 * ed1);

            // ---- reference score (col 0) computed by ALL lanes: no branch --
            float P0b = __shfl_sync(0xffffffffu, P0, 0);
            prev_score = fmaf(lg2f(P0b), LN2, mref) + em0 * mk;

            mref      = mref_next;
            mref_next = mpf;
        }

        if (c + 2 < NCHUNK) issue_chunk(c + 2);
    }

    // ---------------- peeled last step (s = S-1) ----------------
    {
        const int s   = CRF_S - 1;
        const int cb  = (NCHUNK - 1) & 1;
        const int idx = s & (CHUNK - 1);
        float2 em = *reinterpret_cast<const float2*>(&sEm[cb][idx][c0]);
        float  mk = sMk[cb][idx];

        // gold final term
        int   tg = sTg[cb][idx];
        float ge = sEm[cb][idx][tg];
        float gt = __ldg(trans + tg * CRF_T + tgp);
        g = fmaf(gt + ge, mk, g);

        __syncwarp();

        const ulonglong2* E2 = reinterpret_cast<const ulonglong2*>(sE[s & 1]);
        u64 a0 = 0ull, a1 = 0ull, b0 = 0ull, b1 = 0ull;
        #pragma unroll
        for (int k = 0; k < CRF_T / 4; k++) {
            ulonglong2 v = E2[k];
            a0 = ffma2(v.x, tA[2 * k],     a0);
            a1 = ffma2(v.y, tA[2 * k + 1], a1);
            b0 = ffma2(v.x, tB[2 * k],     b0);
            b1 = ffma2(v.y, tB[2 * k + 1], b1);
        }
        u64 ta  = fadd2(a0, a1);
        u64 tb2 = fadd2(b0, b1);
        float xa, ya, xb, yb;
        unpack2(ta, xa, ya); unpack2(tb2, xb, yb);

        float sc0 = fmaf(lg2f(xa + ya), LN2, mref) + em.x * mk;
        float sc1 = fmaf(lg2f(xb + yb), LN2, mref) + em.y * mk;

        // final logsumexp over 64 states, in-warp
        float m = fmaxf(sc0, sc1);
        #pragma unroll
        for (int off = 16; off; off >>= 1)
            m = fmaxf(m, __shfl_xor_sync(0xffffffffu, m, off));

        float e = ex2f((sc0 - m) * LOG2E) + ex2f((sc1 - m) * LOG2E);
        #pragma unroll
        for (int off = 16; off; off >>= 1)
            e += __shfl_xor_sync(0xffffffffu, e, off);

        if (l == 0) {
            float fwd = fmaf(lg2f(e), LN2, m);
            g_partial[b] = fwd - g;
        }
    }

    // ---------------- last-arriving block reduces the mean -------------------
    bool last = false;
    if (l == 0) {
        __threadfence();
        int c = atomicAdd(&g_count, 1);
        last = (c == CRF_B - 1);
        if (last) g_count = 0;              // reset for graph replay
    }
    last = __shfl_sync(0xffffffffu, last, 0);
    if (last) {
        __threadfence();
        float v = 0.f;
        #pragma unroll
        for (int i = 0; i < CRF_B / 32; i++)
            v += g_partial[i * 32 + l];
        #pragma unroll
        for (int off = 16; off; off >>= 1)
            v += __shfl_xor_sync(0xffffffffu, v, off);
        if (l == 0) out[0] = v * (1.0f / CRF_B);
    }
}

extern "C" void kernel_launch(void* const* d_in, const int* in_sizes, int n_in,
                              void* d_out, int out_size)
{
    const float* emis  = (const float*)d_in[0];
    const int*   tags  = (const int*)  d_in[1];
    const float* mask  = (const float*)d_in[2];
    const float* trans = (const float*)d_in[3];

    crf_main<<<CRF_B, 32>>>(emis, tags, mask, trans, (float*)d_out);
}